// round 11
// baseline (speedup 1.0000x reference)
#include <cuda_runtime.h>
#include <cuda_bf16.h>

// pixel_shuffle(x2) + depthwise 4x4 FIR ([1,3,3,1] outer / 64), pad=2.
// x: [16,128,128,128] f32 -> out: [16,32,257,257] f32
//
// Smem-free polyphase design, row loop UNROLLED x4:
//  - each warp owns a 30-wide emitted column chunk (32 lanes incl. halo)
//  - marches down row-pairs with rolling scalar registers
//  - per body: 16 front-batched coalesced LDG.32 (MLP=16), four row-pair
//    computations, P/Q-factored horizontal combine via warp shuffle, dense
//    float2 stores with per-row packing phase chosen by address parity.
//  - row partition 32/32/32/33: 8 bodies/warp, single peeled tail (a=128).
// R11 delta: __launch_bounds__(128, 9) — R10 sat exactly on the 8-CTA
// occupancy cap (48.4% achieved vs 50% cap) with issue idle 55%; 9 CTAs fit
// at 56 regs (9*128*56 = 64512 <= 64K) and the kernel uses 55.

__device__ __forceinline__ float ldz(const float* __restrict__ p, int h, bool colok)
{
    return (colok & ((unsigned)h < 128u)) ? __ldg(p + h * 128) : 0.0f;
}

__global__ __launch_bounds__(128, 9)
void upsampler_kernel(const float* __restrict__ x, float* __restrict__ out)
{
    const unsigned FULL = 0xffffffffu;
    const int chunk = blockIdx.x;          // 0..4   (col chunks of 30 emitted w)
    const int c     = blockIdx.y;          // 0..31  output channel
    const int b     = blockIdx.z;          // 0..15  batch
    const int warp  = threadIdx.x >> 5;    // 0..3
    const int lane  = threadIdx.x & 31;

    const int w = chunk * 30 - 1 + lane;               // -1 .. 149
    const bool colok = (unsigned)w < 128u;

    // sub-channel planes: 0=(er,ec) 1=(er,oc) 2=(or,ec) 3=(or,oc)
    const float* base = x + (size_t)(b * 128 + c * 4) * 16384;
    const float* p0 = base + w;
    const float* p1 = base + 16384 + w;
    const float* p2 = base + 32768 + w;
    const float* p3 = base + 49152 + w;

    const int bc = b * 32 + c;
    float* obase = out + (size_t)bc * 66049;           // 257*257
    const bool mis_even = (bc & 1) != 0;               // even rows misaligned?
    const bool mis_odd  = !mis_even;

    const int a0 = warp * 32;                          // 0,32,64,96
    const int nbody = 8;                               // 32 pairs per warp
    const bool tail = (warp == 3);                     // + a=128 peeled

    const float c1 = 1.0f / 64.0f;
    const float c3 = 3.0f / 64.0f;
    const bool emit = (lane >= 1) && (lane <= 30);

    // one row-pair computation + stores
    auto iter = [&](int a,
                    float A0, float A1, float A2, float B0, float B1,
                    float C0, float C1, float C2, float D0, float D1)
    {
        // vertical 2-tap polyphase, scale 1/64 folded in
        float ve0 = fmaf(c3, A1 + B0, c1 * (A0 + B1));
        float vo0 = fmaf(c3, A1 + B1, c1 * (A2 + B0));
        float ve1 = fmaf(c3, C1 + D0, c1 * (C0 + D1));
        float vo1 = fmaf(c3, C1 + D1, c1 * (C2 + D0));

        // P/Q/R horizontal factorization
        float Pe = fmaf(3.0f, ve1, ve0);
        float Qe = fmaf(3.0f, ve0, ve1);
        float Re = 3.0f * (ve0 + ve1);
        float Po = fmaf(3.0f, vo1, vo0);
        float Qo = fmaf(3.0f, vo0, vo1);
        float Ro = 3.0f * (vo0 + vo1);

        float Pem  = __shfl_up_sync(FULL, Pe, 1);
        float ve1m = __shfl_up_sync(FULL, ve1, 1);
        float ve0p = __shfl_down_sync(FULL, ve0, 1);
        float Pom  = __shfl_up_sync(FULL, Po, 1);
        float vo1m = __shfl_up_sync(FULL, vo1, 1);
        float vo0p = __shfl_down_sync(FULL, vo0, 1);

        float* rowe = obase + (size_t)(2 * a) * 257;

        // even output row 2a (always valid)
        {
            float E = Pem + Qe;
            if (!mis_even) {
                if (emit && w <= 127) {
                    float O = ve0p + Re + ve1m;
                    *reinterpret_cast<float2*>(rowe + 2 * w) = make_float2(E, O);
                } else if (emit && w == 128) {
                    rowe[256] = E;
                }
            } else {
                float En = __shfl_down_sync(FULL, E, 1);
                if (emit && w == 0) rowe[0] = E;
                if (emit && w <= 127) {
                    float O = ve0p + Re + ve1m;
                    *reinterpret_cast<float2*>(rowe + 2 * w + 1) = make_float2(O, En);
                }
            }
        }

        // odd output row 2a+1 (valid for a<=127)
        if (a <= 127) {
            float* rowo = rowe + 257;
            float E = Pom + Qo;
            if (!mis_odd) {
                if (emit && w <= 127) {
                    float O = vo0p + Ro + vo1m;
                    *reinterpret_cast<float2*>(rowo + 2 * w) = make_float2(E, O);
                } else if (emit && w == 128) {
                    rowo[256] = E;
                }
            } else {
                float En = __shfl_down_sync(FULL, E, 1);
                if (emit && w == 0) rowo[0] = E;
                if (emit && w <= 127) {
                    float O = vo0p + Ro + vo1m;
                    *reinterpret_cast<float2*>(rowo + 2 * w + 1) = make_float2(O, En);
                }
            }
        }
    };

    // rolling state: A=plane0 rows a-1..a+2, B=plane2 rows a-1..a+1 (and C/D)
    float A0 = ldz(p0, a0 - 1, colok), A1 = ldz(p0, a0, colok);
    float A2 = ldz(p0, a0 + 1, colok), A3 = ldz(p0, a0 + 2, colok);
    float B0 = ldz(p2, a0 - 1, colok), B1 = ldz(p2, a0, colok), B2 = ldz(p2, a0 + 1, colok);
    float C0 = ldz(p1, a0 - 1, colok), C1 = ldz(p1, a0, colok);
    float C2 = ldz(p1, a0 + 1, colok), C3 = ldz(p1, a0 + 2, colok);
    float D0 = ldz(p3, a0 - 1, colok), D1 = ldz(p3, a0, colok), D2 = ldz(p3, a0 + 1, colok);

    int a = a0;
    #pragma unroll 2
    for (int body = 0; body < nbody; ++body, a += 4) {
        // prefetch: 16 independent front-batched LDGs
        //   A plane rows a+3..a+6, B plane rows a+2..a+5 (and C/D mirrors)
        float nA0 = ldz(p0, a + 3, colok), nA1 = ldz(p0, a + 4, colok);
        float nA2 = ldz(p0, a + 5, colok), nA3 = ldz(p0, a + 6, colok);
        float nB0 = ldz(p2, a + 2, colok), nB1 = ldz(p2, a + 3, colok);
        float nB2 = ldz(p2, a + 4, colok), nB3 = ldz(p2, a + 5, colok);
        float nC0 = ldz(p1, a + 3, colok), nC1 = ldz(p1, a + 4, colok);
        float nC2 = ldz(p1, a + 5, colok), nC3 = ldz(p1, a + 6, colok);
        float nD0 = ldz(p3, a + 2, colok), nD1 = ldz(p3, a + 3, colok);
        float nD2 = ldz(p3, a + 4, colok), nD3 = ldz(p3, a + 5, colok);

        iter(a,     A0,  A1,  A2,  B0,  B1,  C0,  C1,  C2,  D0,  D1);
        iter(a + 1, A1,  A2,  A3,  B1,  B2,  C1,  C2,  C3,  D1,  D2);
        iter(a + 2, A2,  A3,  nA0, B2,  nB0, C2,  C3,  nC0, D2,  nD0);
        iter(a + 3, A3,  nA0, nA1, nB0, nB1, C3,  nC0, nC1, nD0, nD1);

        // rotate to rows a+3.. for next body
        A0 = nA0; A1 = nA1; A2 = nA2; A3 = nA3;
        B0 = nB1; B1 = nB2; B2 = nB3;
        C0 = nC0; C1 = nC1; C2 = nC2; C3 = nC3;
        D0 = nD1; D1 = nD2; D2 = nD3;
    }
    if (tail)   // a = 128 (even output row 256 only)
        iter(a, A0, A1, A2, B0, B1, C0, C1, C2, D0, D1);
}

extern "C" void kernel_launch(void* const* d_in, const int* in_sizes, int n_in,
                              void* d_out, int out_size)
{
    const float* x = (const float*)d_in[0];
    // d_in[1] is the 4x4 kernel == outer([1,3,3,1])/64, hardcoded via the
    // separable polyphase coefficients above.
    float* out = (float*)d_out;
    dim3 grid(5, 32, 16);      // col chunks x channels x batch
    upsampler_kernel<<<grid, 128>>>(x, out);
}

// round 12
// speedup vs baseline: 1.0119x; 1.0119x over previous
#include <cuda_runtime.h>
#include <cuda_bf16.h>

// pixel_shuffle(x2) + depthwise 4x4 FIR ([1,3,3,1] outer / 64), pad=2.
// x: [16,128,128,128] f32 -> out: [16,32,257,257] f32
//
// Smem-free polyphase design, row loop UNROLLED x4:
//  - each warp owns a 30-wide emitted column chunk (32 lanes incl. halo)
//  - marches down row-pairs with rolling scalar registers
//  - per body: 16 front-batched coalesced LDG.32 (MLP=16), four row-pair
//    computations, P/Q-factored horizontal combine via warp shuffle, dense
//    float2 stores with per-row packing phase chosen by address parity.
//  - row partition 32/32/32/33: 8 bodies/warp, single peeled tail (a=128).
// R12 deltas: outer '#pragma unroll 2' removed (live-range + I$ relief) and
// __launch_bounds__(128, 10) -> regs capped at 51, residency cap 40 warps/SM
// (62.5%), waves 2.16 -> 1.73. Discriminates latency-bound vs DRAM-ceiling.

__device__ __forceinline__ float ldz(const float* __restrict__ p, int h, bool colok)
{
    return (colok & ((unsigned)h < 128u)) ? __ldg(p + h * 128) : 0.0f;
}

__global__ __launch_bounds__(128, 10)
void upsampler_kernel(const float* __restrict__ x, float* __restrict__ out)
{
    const unsigned FULL = 0xffffffffu;
    const int chunk = blockIdx.x;          // 0..4   (col chunks of 30 emitted w)
    const int c     = blockIdx.y;          // 0..31  output channel
    const int b     = blockIdx.z;          // 0..15  batch
    const int warp  = threadIdx.x >> 5;    // 0..3
    const int lane  = threadIdx.x & 31;

    const int w = chunk * 30 - 1 + lane;               // -1 .. 149
    const bool colok = (unsigned)w < 128u;

    // sub-channel planes: 0=(er,ec) 1=(er,oc) 2=(or,ec) 3=(or,oc)
    const float* base = x + (size_t)(b * 128 + c * 4) * 16384;
    const float* p0 = base + w;
    const float* p1 = base + 16384 + w;
    const float* p2 = base + 32768 + w;
    const float* p3 = base + 49152 + w;

    const int bc = b * 32 + c;
    float* obase = out + (size_t)bc * 66049;           // 257*257
    const bool mis_even = (bc & 1) != 0;               // even rows misaligned?
    const bool mis_odd  = !mis_even;

    const int a0 = warp * 32;                          // 0,32,64,96
    const int nbody = 8;                               // 32 pairs per warp
    const bool tail = (warp == 3);                     // + a=128 peeled

    const float c1 = 1.0f / 64.0f;
    const float c3 = 3.0f / 64.0f;
    const bool emit = (lane >= 1) && (lane <= 30);

    // one row-pair computation + stores
    auto iter = [&](int a,
                    float A0, float A1, float A2, float B0, float B1,
                    float C0, float C1, float C2, float D0, float D1)
    {
        // vertical 2-tap polyphase, scale 1/64 folded in
        float ve0 = fmaf(c3, A1 + B0, c1 * (A0 + B1));
        float vo0 = fmaf(c3, A1 + B1, c1 * (A2 + B0));
        float ve1 = fmaf(c3, C1 + D0, c1 * (C0 + D1));
        float vo1 = fmaf(c3, C1 + D1, c1 * (C2 + D0));

        // P/Q/R horizontal factorization
        float Pe = fmaf(3.0f, ve1, ve0);
        float Qe = fmaf(3.0f, ve0, ve1);
        float Re = 3.0f * (ve0 + ve1);
        float Po = fmaf(3.0f, vo1, vo0);
        float Qo = fmaf(3.0f, vo0, vo1);
        float Ro = 3.0f * (vo0 + vo1);

        float Pem  = __shfl_up_sync(FULL, Pe, 1);
        float ve1m = __shfl_up_sync(FULL, ve1, 1);
        float ve0p = __shfl_down_sync(FULL, ve0, 1);
        float Pom  = __shfl_up_sync(FULL, Po, 1);
        float vo1m = __shfl_up_sync(FULL, vo1, 1);
        float vo0p = __shfl_down_sync(FULL, vo0, 1);

        float* rowe = obase + (size_t)(2 * a) * 257;

        // even output row 2a (always valid)
        {
            float E = Pem + Qe;
            if (!mis_even) {
                if (emit && w <= 127) {
                    float O = ve0p + Re + ve1m;
                    *reinterpret_cast<float2*>(rowe + 2 * w) = make_float2(E, O);
                } else if (emit && w == 128) {
                    rowe[256] = E;
                }
            } else {
                float En = __shfl_down_sync(FULL, E, 1);
                if (emit && w == 0) rowe[0] = E;
                if (emit && w <= 127) {
                    float O = ve0p + Re + ve1m;
                    *reinterpret_cast<float2*>(rowe + 2 * w + 1) = make_float2(O, En);
                }
            }
        }

        // odd output row 2a+1 (valid for a<=127)
        if (a <= 127) {
            float* rowo = rowe + 257;
            float E = Pom + Qo;
            if (!mis_odd) {
                if (emit && w <= 127) {
                    float O = vo0p + Ro + vo1m;
                    *reinterpret_cast<float2*>(rowo + 2 * w) = make_float2(E, O);
                } else if (emit && w == 128) {
                    rowo[256] = E;
                }
            } else {
                float En = __shfl_down_sync(FULL, E, 1);
                if (emit && w == 0) rowo[0] = E;
                if (emit && w <= 127) {
                    float O = vo0p + Ro + vo1m;
                    *reinterpret_cast<float2*>(rowo + 2 * w + 1) = make_float2(O, En);
                }
            }
        }
    };

    // rolling state: A=plane0 rows a-1..a+2, B=plane2 rows a-1..a+1 (and C/D)
    float A0 = ldz(p0, a0 - 1, colok), A1 = ldz(p0, a0, colok);
    float A2 = ldz(p0, a0 + 1, colok), A3 = ldz(p0, a0 + 2, colok);
    float B0 = ldz(p2, a0 - 1, colok), B1 = ldz(p2, a0, colok), B2 = ldz(p2, a0 + 1, colok);
    float C0 = ldz(p1, a0 - 1, colok), C1 = ldz(p1, a0, colok);
    float C2 = ldz(p1, a0 + 1, colok), C3 = ldz(p1, a0 + 2, colok);
    float D0 = ldz(p3, a0 - 1, colok), D1 = ldz(p3, a0, colok), D2 = ldz(p3, a0 + 1, colok);

    int a = a0;
    for (int body = 0; body < nbody; ++body, a += 4) {
        // prefetch: 16 independent front-batched LDGs
        //   A plane rows a+3..a+6, B plane rows a+2..a+5 (and C/D mirrors)
        float nA0 = ldz(p0, a + 3, colok), nA1 = ldz(p0, a + 4, colok);
        float nA2 = ldz(p0, a + 5, colok), nA3 = ldz(p0, a + 6, colok);
        float nB0 = ldz(p2, a + 2, colok), nB1 = ldz(p2, a + 3, colok);
        float nB2 = ldz(p2, a + 4, colok), nB3 = ldz(p2, a + 5, colok);
        float nC0 = ldz(p1, a + 3, colok), nC1 = ldz(p1, a + 4, colok);
        float nC2 = ldz(p1, a + 5, colok), nC3 = ldz(p1, a + 6, colok);
        float nD0 = ldz(p3, a + 2, colok), nD1 = ldz(p3, a + 3, colok);
        float nD2 = ldz(p3, a + 4, colok), nD3 = ldz(p3, a + 5, colok);

        iter(a,     A0,  A1,  A2,  B0,  B1,  C0,  C1,  C2,  D0,  D1);
        iter(a + 1, A1,  A2,  A3,  B1,  B2,  C1,  C2,  C3,  D1,  D2);
        iter(a + 2, A2,  A3,  nA0, B2,  nB0, C2,  C3,  nC0, D2,  nD0);
        iter(a + 3, A3,  nA0, nA1, nB0, nB1, C3,  nC0, nC1, nD0, nD1);

        // rotate to rows a+3.. for next body
        A0 = nA0; A1 = nA1; A2 = nA2; A3 = nA3;
        B0 = nB1; B1 = nB2; B2 = nB3;
        C0 = nC0; C1 = nC1; C2 = nC2; C3 = nC3;
        D0 = nD1; D1 = nD2; D2 = nD3;
    }
    if (tail)   // a = 128 (even output row 256 only)
        iter(a, A0, A1, A2, B0, B1, C0, C1, C2, D0, D1);
}

extern "C" void kernel_launch(void* const* d_in, const int* in_sizes, int n_in,
                              void* d_out, int out_size)
{
    const float* x = (const float*)d_in[0];
    // d_in[1] is the 4x4 kernel == outer([1,3,3,1])/64, hardcoded via the
    // separable polyphase coefficients above.
    float* out = (float*)d_out;
    dim3 grid(5, 32, 16);      // col chunks x channels x batch
    upsampler_kernel<<<grid, 128>>>(x, out);
}